// round 9
// baseline (speedup 1.0000x reference)
#include <cuda_runtime.h>
#include <cuda_fp16.h>
#include <math.h>
#include <stdint.h>

#define N_PTS 524288
#define N_TILES (N_PTS / 128)

// ---------------- scratch (device globals; no allocation) ----------------
__device__ float4 d_g0t[32 * 32 * 32];
__device__ float4 d_g1t[64 * 64 * 64];
__device__ float4 d_g2t[128 * 128 * 128];
__device__ float4 d_g3t[256 * 256 * 256];
__device__ float4 d_coeft[64 * 64 * 64];
// compact packed weights: layer0 (kstep=0 only) 4KB, layers 1-6 32KB each.
// fragment uint4 = {B(j).b0, B(j).b1, B(j+1).b0, B(j+1).b1} (fp16x2 each),
// mma.m16n8k16 col-B layout, j = 2*jpair, index ((kstep*8+jp)*32+lane).
#define WPACK_TOTAL (4096 + 6 * 32768)
__device__ __align__(16) unsigned char d_wpack[WPACK_TOTAL];

// ================= helpers =================
__device__ __forceinline__ uint32_t smem_to_u32(const void* p) {
    uint32_t a;
    asm("{ .reg .u64 t; cvta.to.shared.u64 t, %1; cvt.u32.u64 %0, t; }"
        : "=r"(a) : "l"(p));
    return a;
}
__device__ __forceinline__ uint32_t cvt_f16x2(float v0, float v1) {
    uint32_t d;
    asm("cvt.rn.f16x2.f32 %0, %1, %2;" : "=r"(d) : "f"(v1), "f"(v0));
    return d;
}
__device__ __forceinline__ void mma_fp16(float* c, const uint32_t* a,
                                         uint32_t b0, uint32_t b1) {
    asm volatile(
        "mma.sync.aligned.m16n8k16.row.col.f32.f16.f16.f32 "
        "{%0,%1,%2,%3}, {%4,%5,%6,%7}, {%8,%9}, {%0,%1,%2,%3};"
        : "+f"(c[0]), "+f"(c[1]), "+f"(c[2]), "+f"(c[3])
        : "r"(a[0]), "r"(a[1]), "r"(a[2]), "r"(a[3]), "r"(b0), "r"(b1));
}
__device__ __forceinline__ void cp_async16(uint32_t smem_dst, const void* gsrc) {
    asm volatile("cp.async.cg.shared.global [%0], [%1], 16;"
                 :: "r"(smem_dst), "l"(gsrc));
}
__device__ __forceinline__ void cp_commit() {
    asm volatile("cp.async.commit_group;" ::: "memory");
}
__device__ __forceinline__ void cp_wait_all() {
    asm volatile("cp.async.wait_group 0;" ::: "memory");
}
#define GROUP_BAR(gid) \
    asm volatile("bar.sync %0, 256;" :: "r"(1 + (gid)) : "memory")

// ---------------- channels-last transpose: [4,V] -> [V] float4 ----------------
__global__ void transpose_cl(const float* __restrict__ src, float4* __restrict__ dst, int V) {
    int v = blockIdx.x * blockDim.x + threadIdx.x;
    if (v < V) {
        dst[v] = make_float4(src[v], src[v + V], src[v + 2 * V], src[v + 3 * V]);
    }
}

// ---------------- weight packer ----------------
struct MLPW {
    const float* W[7];
    const float* B[7];
};

// fragment layout for mma.m16n8k16 row.col, B is [K,128] row-major in memory:
// b0 = {B[k0][n], B[k0+1][n]}, b1 = {B[k0+8][n], B[k0+9][n]},
// k0 = 16*kstep + 2*(lane&3), n = 8*ntile + (lane>>2). Single fp16.
// Paired: ntile=2*jp, 2*jp+1 adjacent in one uint4. Compact per-layer offsets.
__global__ void pack_weights(MLPW p) {
    int t = blockIdx.x * blockDim.x + threadIdx.x;
    if (t >= 7 * 8 * 16 * 32) return;
    int l     = t >> 12;
    int r     = t & 4095;
    int kstep = r >> 9;
    int ntile = (r >> 5) & 15;
    int lane  = r & 31;
    if (l == 0 && kstep > 0) return;   // layer 0 has K=16 only

    int n  = ntile * 8 + (lane >> 2);
    int k0 = kstep * 16 + 2 * (lane & 3);
    const float* W = p.W[l];
    uint2 frag;
    frag.x = cvt_f16x2(W[(k0 + 0) * 128 + n], W[(k0 + 1) * 128 + n]);
    frag.y = cvt_f16x2(W[(k0 + 8) * 128 + n], W[(k0 + 9) * 128 + n]);

    int jp   = ntile >> 1;
    int half = ntile & 1;
    size_t loff = (l == 0) ? 0 : (size_t)4096 + (size_t)(l - 1) * 32768;
    size_t off  = loff + (((size_t)(kstep * 8 + jp) * 32 + lane) * 16) + half * 8;
    *(uint2*)(d_wpack + off) = frag;
}

// ---------------- trilerp on channels-last grid ----------------
__device__ __forceinline__ float4 trilerp4(const float4* __restrict__ g, int R,
                                           float px, float py, float pz) {
    float s = 0.5f * (float)(R - 1);
    float cx = (px + 1.0f) * s;
    float cy = (py + 1.0f) * s;
    float cz = (pz + 1.0f) * s;
    float fx0 = floorf(cx), fy0 = floorf(cy), fz0 = floorf(cz);
    float fx = cx - fx0, fy = cy - fy0, fz = cz - fz0;
    int x0 = min(max((int)fx0, 0), R - 1);
    int y0 = min(max((int)fy0, 0), R - 1);
    int z0 = min(max((int)fz0, 0), R - 1);
    int x1 = min(x0 + 1, R - 1);
    int y1 = min(y0 + 1, R - 1);
    int z1 = min(z0 + 1, R - 1);

    const float4 v000 = __ldg(&g[(z0 * R + y0) * R + x0]);
    const float4 v001 = __ldg(&g[(z0 * R + y0) * R + x1]);
    const float4 v010 = __ldg(&g[(z0 * R + y1) * R + x0]);
    const float4 v011 = __ldg(&g[(z0 * R + y1) * R + x1]);
    const float4 v100 = __ldg(&g[(z1 * R + y0) * R + x0]);
    const float4 v101 = __ldg(&g[(z1 * R + y0) * R + x1]);
    const float4 v110 = __ldg(&g[(z1 * R + y1) * R + x0]);
    const float4 v111 = __ldg(&g[(z1 * R + y1) * R + x1]);

    float gx = 1.0f - fx, gy = 1.0f - fy, gz = 1.0f - fz;
    float w00 = gz * gy, w01 = gz * fy, w10 = fz * gy, w11 = fz * fy;

    float4 r;
    r.x = (v000.x * gx + v001.x * fx) * w00 + (v010.x * gx + v011.x * fx) * w01
        + (v100.x * gx + v101.x * fx) * w10 + (v110.x * gx + v111.x * fx) * w11;
    r.y = (v000.y * gx + v001.y * fx) * w00 + (v010.y * gx + v011.y * fx) * w01
        + (v100.y * gx + v101.y * fx) * w10 + (v110.y * gx + v111.y * fx) * w11;
    r.z = (v000.z * gx + v001.z * fx) * w00 + (v010.z * gx + v011.z * fx) * w01
        + (v100.z * gx + v101.z * fx) * w10 + (v110.z * gx + v111.z * fx) * w11;
    r.w = (v000.w * gx + v001.w * fx) * w00 + (v010.w * gx + v011.w * fx) * w01
        + (v100.w * gx + v101.w * fx) * w10 + (v110.w * gx + v111.w * fx) * w11;
    return r;
}

__device__ __forceinline__ float fracf(float a) { return a - floorf(a); }

// ---------------- persistent weight-stationary fused encode+MLP ----------------
// Grid = 148 persistent CTAs x 512 threads (16 warps). All 7 layers' weights
// (196KB) + biases resident in smem; loaded once per CTA. Two groups of 8
// warps process interleaved 128-pt tiles independently (named barriers), so
// group A's gather-bound encode overlaps group B's tensor-bound MMA chain.
#define SM_BIAS 200704               // 196KB weights end
#define SM_FEAT (SM_BIAS + 3584)     // 7*512B bias
#define SM_DYN  (SM_FEAT + 2 * 8192) // 2 groups x [16][128] f32

__global__ void __launch_bounds__(512, 1) mlp_mma(MLPW p, const float* __restrict__ x,
                                                  float* __restrict__ out) {
    extern __shared__ char smem[];
    const int tid   = threadIdx.x;
    const int grp   = tid >> 8;       // 0 or 1
    const int gtid  = tid & 255;      // thread id within group
    const int gwid  = gtid >> 5;      // warp id within group (0-7)
    const int lane  = tid & 31;
    const int qrow  = lane >> 2;
    const int tc    = lane & 3;
    const uint32_t sb = smem_to_u32(smem);

    // --- load ALL weights (196KB) + biases once ---
    for (int i = tid; i < WPACK_TOTAL / 16; i += 512)
        cp_async16(sb + 16 * i, d_wpack + 16 * (size_t)i);
    if (tid < 224) {
        int l = tid >> 5;
        int i = tid & 31;
        cp_async16(sb + SM_BIAS + l * 512 + 16 * i, (const char*)p.B[l] + 16 * i);
    }
    cp_commit();
    cp_wait_all();
    __syncthreads();

    float* sfeat = (float*)(smem + SM_FEAT + grp * 8192);   // [16][128]

    for (int tile = blockIdx.x * 2 + grp; tile < N_TILES; tile += 2 * gridDim.x) {
        const int base = tile * 128;

        // --- encode: 2 threads per point (256 threads, 128 points) ---
        {
            const int half = gtid >> 7;
            const int pl   = gtid & 127;
            const int i    = base + pl;
            float px = x[3 * i + 0];
            float py = x[3 * i + 1];
            float pz = x[3 * i + 2];
            float4 coef = trilerp4(d_coeft, 64, px, py, pz);

            if (half == 0) {
                {
                    float ex = 2.0f * fracf(px) - 1.0f;
                    float ey = 2.0f * fracf(py) - 1.0f;
                    float ez = 2.0f * fracf(pz) - 1.0f;
                    float4 v = trilerp4(d_g0t, 32, ex, ey, ez);
                    sfeat[0 * 128 + pl] = v.x * coef.x;
                    sfeat[1 * 128 + pl] = v.y * coef.x;
                    sfeat[2 * 128 + pl] = v.z * coef.x;
                    sfeat[3 * 128 + pl] = v.w * coef.x;
                }
                {
                    float ex = 2.0f * fracf(px * 2.0f) - 1.0f;
                    float ey = 2.0f * fracf(py * 2.0f) - 1.0f;
                    float ez = 2.0f * fracf(pz * 2.0f) - 1.0f;
                    float4 v = trilerp4(d_g1t, 64, ex, ey, ez);
                    sfeat[4 * 128 + pl] = v.x * coef.y;
                    sfeat[5 * 128 + pl] = v.y * coef.y;
                    sfeat[6 * 128 + pl] = v.z * coef.y;
                    sfeat[7 * 128 + pl] = v.w * coef.y;
                }
            } else {
                {
                    float ex = 2.0f * fracf(px * 4.0f) - 1.0f;
                    float ey = 2.0f * fracf(py * 4.0f) - 1.0f;
                    float ez = 2.0f * fracf(pz * 4.0f) - 1.0f;
                    float4 v = trilerp4(d_g2t, 128, ex, ey, ez);
                    sfeat[8 * 128 + pl]  = v.x * coef.z;
                    sfeat[9 * 128 + pl]  = v.y * coef.z;
                    sfeat[10 * 128 + pl] = v.z * coef.z;
                    sfeat[11 * 128 + pl] = v.w * coef.z;
                }
                {
                    float ex = 2.0f * fracf(px * 8.0f) - 1.0f;
                    float ey = 2.0f * fracf(py * 8.0f) - 1.0f;
                    float ez = 2.0f * fracf(pz * 8.0f) - 1.0f;
                    float4 v = trilerp4(d_g3t, 256, ex, ey, ez);
                    sfeat[12 * 128 + pl] = v.x * coef.w;
                    sfeat[13 * 128 + pl] = v.y * coef.w;
                    sfeat[14 * 128 + pl] = v.z * coef.w;
                    sfeat[15 * 128 + pl] = v.w * coef.w;
                }
            }
        }
        GROUP_BAR(grp);

        // --- layer-0 A fragments (single fp16), kstep 0 only ---
        uint32_t af[8][4];
        {
            const int k0  = 2 * tc;
            const int rl0 = gwid * 16 + qrow;
            const int rl1 = rl0 + 8;
            af[0][0] = cvt_f16x2(sfeat[(k0 + 0) * 128 + rl0], sfeat[(k0 + 1) * 128 + rl0]);
            af[0][1] = cvt_f16x2(sfeat[(k0 + 0) * 128 + rl1], sfeat[(k0 + 1) * 128 + rl1]);
            af[0][2] = cvt_f16x2(sfeat[(k0 + 8) * 128 + rl0], sfeat[(k0 + 9) * 128 + rl0]);
            af[0][3] = cvt_f16x2(sfeat[(k0 + 8) * 128 + rl1], sfeat[(k0 + 9) * 128 + rl1]);
        }
        GROUP_BAR(grp);   // sfeat reads done before next tile's encode

        const int r0 = base + gwid * 16 + qrow;
        const int r1 = r0 + 8;

        for (int l = 0; l < 7; l++) {
            const int K16 = (l == 0) ? 1 : 8;
            const uint32_t woff = (l == 0) ? 0u : 4096u + (uint32_t)(l - 1) * 32768u;
            const uint4* wf = (const uint4*)(smem + woff);
            const float* bs = (const float*)(smem + SM_BIAS + l * 512);

            float acc[16][4];
#pragma unroll
            for (int j = 0; j < 16; j++)
#pragma unroll
                for (int q = 0; q < 4; q++) acc[j][q] = 0.0f;

#pragma unroll 1
            for (int ks = 0; ks < K16; ks++) {
#pragma unroll
                for (int jp = 0; jp < 8; jp++) {
                    uint4 w = wf[(ks * 8 + jp) * 32 + lane];
                    mma_fp16(acc[2 * jp],     af[ks], w.x, w.y);
                    mma_fp16(acc[2 * jp + 1], af[ks], w.z, w.w);
                }
            }

            if (l < 6) {
                // bias + relu, repack D -> next-layer A fragments (lane-local)
#pragma unroll
                for (int j = 0; j < 16; j++) {
                    float b0 = bs[8 * j + 2 * tc];
                    float b1 = bs[8 * j + 2 * tc + 1];
                    acc[j][0] = fmaxf(acc[j][0] + b0, 0.0f);
                    acc[j][1] = fmaxf(acc[j][1] + b1, 0.0f);
                    acc[j][2] = fmaxf(acc[j][2] + b0, 0.0f);
                    acc[j][3] = fmaxf(acc[j][3] + b1, 0.0f);
                }
#pragma unroll
                for (int t = 0; t < 8; t++) {
                    af[t][0] = cvt_f16x2(acc[2 * t][0],     acc[2 * t][1]);
                    af[t][1] = cvt_f16x2(acc[2 * t][2],     acc[2 * t][3]);
                    af[t][2] = cvt_f16x2(acc[2 * t + 1][0], acc[2 * t + 1][1]);
                    af[t][3] = cvt_f16x2(acc[2 * t + 1][2], acc[2 * t + 1][3]);
                }
            } else {
                float* o0 = out + (size_t)r0 * 128;
                float* o1 = out + (size_t)r1 * 128;
#pragma unroll
                for (int j = 0; j < 16; j++) {
                    const int col = 8 * j + 2 * tc;
                    float b0 = bs[col], b1 = bs[col + 1];
                    float2 v0 = make_float2(acc[j][0] + b0, acc[j][1] + b1);
                    float2 v1 = make_float2(acc[j][2] + b0, acc[j][3] + b1);
                    *(float2*)(o0 + col) = v0;
                    *(float2*)(o1 + col) = v1;
                }
            }
        }
    }
}

// ---------------- launch ----------------
extern "C" void kernel_launch(void* const* d_in, const int* in_sizes, int n_in,
                              void* d_out, int out_size) {
    const float* x    = (const float*)d_in[0];
    const float* g0   = (const float*)d_in[1];
    const float* g1   = (const float*)d_in[2];
    const float* g2   = (const float*)d_in[3];
    const float* g3   = (const float*)d_in[4];
    const float* coef = (const float*)d_in[5];

    MLPW p;
    for (int j = 0; j < 7; j++) {
        p.W[j] = (const float*)d_in[6 + 2 * j];
        p.B[j] = (const float*)d_in[7 + 2 * j];
    }
    float* out = (float*)d_out;

    cudaFuncSetAttribute(mlp_mma, cudaFuncAttributeMaxDynamicSharedMemorySize, SM_DYN);

    void* ptr;
    cudaGetSymbolAddress(&ptr, d_g0t);   float4* g0t = (float4*)ptr;
    cudaGetSymbolAddress(&ptr, d_g1t);   float4* g1t = (float4*)ptr;
    cudaGetSymbolAddress(&ptr, d_g2t);   float4* g2t = (float4*)ptr;
    cudaGetSymbolAddress(&ptr, d_g3t);   float4* g3t = (float4*)ptr;
    cudaGetSymbolAddress(&ptr, d_coeft); float4* ct  = (float4*)ptr;

    transpose_cl<<<(32 * 32 * 32 + 255) / 256, 256>>>(g0, g0t, 32 * 32 * 32);
    transpose_cl<<<(64 * 64 * 64 + 255) / 256, 256>>>(g1, g1t, 64 * 64 * 64);
    transpose_cl<<<(128 * 128 * 128 + 255) / 256, 256>>>(g2, g2t, 128 * 128 * 128);
    transpose_cl<<<(256 * 256 * 256 + 255) / 256, 256>>>(g3, g3t, 256 * 256 * 256);
    transpose_cl<<<(64 * 64 * 64 + 255) / 256, 256>>>(coef, ct, 64 * 64 * 64);

    pack_weights<<<(7 * 8 * 16 * 32 + 255) / 256, 256>>>(p);

    mlp_mma<<<148, 512, SM_DYN>>>(p, x, out);
}

// round 10
// speedup vs baseline: 1.1516x; 1.1516x over previous
#include <cuda_runtime.h>
#include <cuda_fp16.h>
#include <math.h>
#include <stdint.h>

#define N_PTS 524288
#define N_TILES (N_PTS / 128)

// ---------------- scratch (device globals; no allocation) ----------------
__device__ float4 d_g0t[32 * 32 * 32];
__device__ float4 d_g1t[64 * 64 * 64];
__device__ float4 d_g2t[128 * 128 * 128];
__device__ float4 d_g3t[256 * 256 * 256];
__device__ float4 d_coeft[64 * 64 * 64];
// compact packed weights: layer0 (kstep=0 only) 4KB, layers 1-6 32KB each.
// fragment uint4 = {B(j).b0, B(j).b1, B(j+1).b0, B(j+1).b1} (fp16x2 each),
// mma.m16n8k16 col-B layout, j = 2*jpair, index ((kstep*8+jp)*32+lane).
#define WPACK_TOTAL (4096 + 6 * 32768)
__device__ __align__(16) unsigned char d_wpack[WPACK_TOTAL];

// ================= helpers =================
__device__ __forceinline__ uint32_t smem_to_u32(const void* p) {
    uint32_t a;
    asm("{ .reg .u64 t; cvta.to.shared.u64 t, %1; cvt.u32.u64 %0, t; }"
        : "=r"(a) : "l"(p));
    return a;
}
__device__ __forceinline__ uint32_t cvt_f16x2(float v0, float v1) {
    uint32_t d;
    asm("cvt.rn.f16x2.f32 %0, %1, %2;" : "=r"(d) : "f"(v1), "f"(v0));
    return d;
}
__device__ __forceinline__ void mma_fp16(float* c, const uint32_t* a,
                                         uint32_t b0, uint32_t b1) {
    asm volatile(
        "mma.sync.aligned.m16n8k16.row.col.f32.f16.f16.f32 "
        "{%0,%1,%2,%3}, {%4,%5,%6,%7}, {%8,%9}, {%0,%1,%2,%3};"
        : "+f"(c[0]), "+f"(c[1]), "+f"(c[2]), "+f"(c[3])
        : "r"(a[0]), "r"(a[1]), "r"(a[2]), "r"(a[3]), "r"(b0), "r"(b1));
}
__device__ __forceinline__ void cp_async16(uint32_t smem_dst, const void* gsrc) {
    asm volatile("cp.async.cg.shared.global [%0], [%1], 16;"
                 :: "r"(smem_dst), "l"(gsrc));
}
__device__ __forceinline__ void cp_commit() {
    asm volatile("cp.async.commit_group;" ::: "memory");
}
__device__ __forceinline__ void cp_wait_all() {
    asm volatile("cp.async.wait_group 0;" ::: "memory");
}
// consumer-group barrier (named bar 2, 256 threads)
#define CONS_BAR() asm volatile("bar.sync 2, 256;" ::: "memory")

// ---------------- channels-last transpose: [4,V] -> [V] float4 ----------------
__global__ void transpose_cl(const float* __restrict__ src, float4* __restrict__ dst, int V) {
    int v = blockIdx.x * blockDim.x + threadIdx.x;
    if (v < V) {
        dst[v] = make_float4(src[v], src[v + V], src[v + 2 * V], src[v + 3 * V]);
    }
}

// ---------------- weight packer ----------------
struct MLPW {
    const float* W[7];
    const float* B[7];
};

__global__ void pack_weights(MLPW p) {
    int t = blockIdx.x * blockDim.x + threadIdx.x;
    if (t >= 7 * 8 * 16 * 32) return;
    int l     = t >> 12;
    int r     = t & 4095;
    int kstep = r >> 9;
    int ntile = (r >> 5) & 15;
    int lane  = r & 31;
    if (l == 0 && kstep > 0) return;   // layer 0 has K=16 only

    int n  = ntile * 8 + (lane >> 2);
    int k0 = kstep * 16 + 2 * (lane & 3);
    const float* W = p.W[l];
    uint2 frag;
    frag.x = cvt_f16x2(W[(k0 + 0) * 128 + n], W[(k0 + 1) * 128 + n]);
    frag.y = cvt_f16x2(W[(k0 + 8) * 128 + n], W[(k0 + 9) * 128 + n]);

    int jp   = ntile >> 1;
    int half = ntile & 1;
    size_t loff = (l == 0) ? 0 : (size_t)4096 + (size_t)(l - 1) * 32768;
    size_t off  = loff + (((size_t)(kstep * 8 + jp) * 32 + lane) * 16) + half * 8;
    *(uint2*)(d_wpack + off) = frag;
}

// ---------------- trilerp on channels-last grid ----------------
__device__ __forceinline__ float4 trilerp4(const float4* __restrict__ g, int R,
                                           float px, float py, float pz) {
    float s = 0.5f * (float)(R - 1);
    float cx = (px + 1.0f) * s;
    float cy = (py + 1.0f) * s;
    float cz = (pz + 1.0f) * s;
    float fx0 = floorf(cx), fy0 = floorf(cy), fz0 = floorf(cz);
    float fx = cx - fx0, fy = cy - fy0, fz = cz - fz0;
    int x0 = min(max((int)fx0, 0), R - 1);
    int y0 = min(max((int)fy0, 0), R - 1);
    int z0 = min(max((int)fz0, 0), R - 1);
    int x1 = min(x0 + 1, R - 1);
    int y1 = min(y0 + 1, R - 1);
    int z1 = min(z0 + 1, R - 1);

    const float4 v000 = __ldg(&g[(z0 * R + y0) * R + x0]);
    const float4 v001 = __ldg(&g[(z0 * R + y0) * R + x1]);
    const float4 v010 = __ldg(&g[(z0 * R + y1) * R + x0]);
    const float4 v011 = __ldg(&g[(z0 * R + y1) * R + x1]);
    const float4 v100 = __ldg(&g[(z1 * R + y0) * R + x0]);
    const float4 v101 = __ldg(&g[(z1 * R + y0) * R + x1]);
    const float4 v110 = __ldg(&g[(z1 * R + y1) * R + x0]);
    const float4 v111 = __ldg(&g[(z1 * R + y1) * R + x1]);

    float gx = 1.0f - fx, gy = 1.0f - fy, gz = 1.0f - fz;
    float w00 = gz * gy, w01 = gz * fy, w10 = fz * gy, w11 = fz * fy;

    float4 r;
    r.x = (v000.x * gx + v001.x * fx) * w00 + (v010.x * gx + v011.x * fx) * w01
        + (v100.x * gx + v101.x * fx) * w10 + (v110.x * gx + v111.x * fx) * w11;
    r.y = (v000.y * gx + v001.y * fx) * w00 + (v010.y * gx + v011.y * fx) * w01
        + (v100.y * gx + v101.y * fx) * w10 + (v110.y * gx + v111.y * fx) * w11;
    r.z = (v000.z * gx + v001.z * fx) * w00 + (v010.z * gx + v011.z * fx) * w01
        + (v100.z * gx + v101.z * fx) * w10 + (v110.z * gx + v111.z * fx) * w11;
    r.w = (v000.w * gx + v001.w * fx) * w00 + (v010.w * gx + v011.w * fx) * w01
        + (v100.w * gx + v101.w * fx) * w10 + (v110.w * gx + v111.w * fx) * w11;
    return r;
}

__device__ __forceinline__ float fracf(float a) { return a - floorf(a); }

// producer encode: 256 threads, 2 per point, writes [16][128] feats to sfeat
__device__ __forceinline__ void encode_tile(const float* __restrict__ x,
                                            float* sfeat, int base, int ptid) {
    const int half = ptid >> 7;
    const int pl   = ptid & 127;
    const int i    = base + pl;
    float px = x[3 * i + 0];
    float py = x[3 * i + 1];
    float pz = x[3 * i + 2];
    float4 coef = trilerp4(d_coeft, 64, px, py, pz);

    if (half == 0) {
        {
            float ex = 2.0f * fracf(px) - 1.0f;
            float ey = 2.0f * fracf(py) - 1.0f;
            float ez = 2.0f * fracf(pz) - 1.0f;
            float4 v = trilerp4(d_g0t, 32, ex, ey, ez);
            sfeat[0 * 128 + pl] = v.x * coef.x;
            sfeat[1 * 128 + pl] = v.y * coef.x;
            sfeat[2 * 128 + pl] = v.z * coef.x;
            sfeat[3 * 128 + pl] = v.w * coef.x;
        }
        {
            float ex = 2.0f * fracf(px * 2.0f) - 1.0f;
            float ey = 2.0f * fracf(py * 2.0f) - 1.0f;
            float ez = 2.0f * fracf(pz * 2.0f) - 1.0f;
            float4 v = trilerp4(d_g1t, 64, ex, ey, ez);
            sfeat[4 * 128 + pl] = v.x * coef.y;
            sfeat[5 * 128 + pl] = v.y * coef.y;
            sfeat[6 * 128 + pl] = v.z * coef.y;
            sfeat[7 * 128 + pl] = v.w * coef.y;
        }
    } else {
        {
            float ex = 2.0f * fracf(px * 4.0f) - 1.0f;
            float ey = 2.0f * fracf(py * 4.0f) - 1.0f;
            float ez = 2.0f * fracf(pz * 4.0f) - 1.0f;
            float4 v = trilerp4(d_g2t, 128, ex, ey, ez);
            sfeat[8 * 128 + pl]  = v.x * coef.z;
            sfeat[9 * 128 + pl]  = v.y * coef.z;
            sfeat[10 * 128 + pl] = v.z * coef.z;
            sfeat[11 * 128 + pl] = v.w * coef.z;
        }
        {
            float ex = 2.0f * fracf(px * 8.0f) - 1.0f;
            float ey = 2.0f * fracf(py * 8.0f) - 1.0f;
            float ez = 2.0f * fracf(pz * 8.0f) - 1.0f;
            float4 v = trilerp4(d_g3t, 256, ex, ey, ez);
            sfeat[12 * 128 + pl] = v.x * coef.w;
            sfeat[13 * 128 + pl] = v.y * coef.w;
            sfeat[14 * 128 + pl] = v.z * coef.w;
            sfeat[15 * 128 + pl] = v.w * coef.w;
        }
    }
}

// ---------------- persistent producer/consumer fused encode+MLP ----------------
// 148 persistent CTAs x 512 threads. Warps 0-7 (tid<256): producers — encode
// tile t+1 into ping-pong feat buffer (LSU-bound). Warps 8-15: consumers —
// 7-layer MMA chain on tile t with double-buffered 32KB weight staging
// (tensor-bound). One __syncthreads per tile = the handoff. smem kept small
// (86KB) so L1D (~142KB) still caches the encode gathers (R9 lesson).
#define SM_W    0
#define SM_BIAS 65536
#define SM_FEAT (65536 + 3584)
#define SM_DYN  (SM_FEAT + 2 * 8192)

__global__ void __launch_bounds__(512, 1) mlp_mma(MLPW p, const float* __restrict__ x,
                                                  float* __restrict__ out) {
    extern __shared__ char smem[];
    const int tid  = threadIdx.x;
    const int lane = tid & 31;
    const uint32_t sb = smem_to_u32(smem);

    const int nt = (N_TILES - blockIdx.x + gridDim.x - 1) / gridDim.x;

    // prologue: consumers stage layer-0 weights (4KB) + all 7 biases;
    // producers encode tile 0 into feat buffer 0.
    if (tid >= 256) {
        const int ctid = tid - 256;
        cp_async16(sb + SM_W + 16 * ctid, d_wpack + 16 * (size_t)ctid);  // 256x16B = 4KB
        if (ctid < 224)
            cp_async16(sb + SM_BIAS + 16 * ctid, (const char*)p.B[ctid >> 5] + 16 * (ctid & 31));
        cp_commit();
        cp_wait_all();
    } else {
        if (nt > 0)
            encode_tile(x, (float*)(smem + SM_FEAT), blockIdx.x * 128, tid);
    }
    __syncthreads();

    int wcur = 0;   // weight buffer holding layer 0 of the current tile (consumers)

    for (int k = 0; k < nt; k++) {
        if (tid < 256) {
            // ---- producer: encode tile k+1 ----
            if (k + 1 < nt) {
                const int base_p = (blockIdx.x + (k + 1) * gridDim.x) * 128;
                encode_tile(x, (float*)(smem + SM_FEAT + ((k + 1) & 1) * 8192), base_p, tid);
            }
        } else {
            // ---- consumer: 7-layer MLP on tile k ----
            const int ctid = tid - 256;
            const int cwid = ctid >> 5;
            const int qrow = lane >> 2;
            const int tc   = lane & 3;
            const int base = (blockIdx.x + k * gridDim.x) * 128;
            const float* sfeat = (const float*)(smem + SM_FEAT + (k & 1) * 8192);

            // layer-0 A fragments (single fp16), kstep 0 only
            uint32_t af[8][4];
            {
                const int k0  = 2 * tc;
                const int rl0 = cwid * 16 + qrow;
                const int rl1 = rl0 + 8;
                af[0][0] = cvt_f16x2(sfeat[(k0 + 0) * 128 + rl0], sfeat[(k0 + 1) * 128 + rl0]);
                af[0][1] = cvt_f16x2(sfeat[(k0 + 0) * 128 + rl1], sfeat[(k0 + 1) * 128 + rl1]);
                af[0][2] = cvt_f16x2(sfeat[(k0 + 8) * 128 + rl0], sfeat[(k0 + 9) * 128 + rl0]);
                af[0][3] = cvt_f16x2(sfeat[(k0 + 8) * 128 + rl1], sfeat[(k0 + 9) * 128 + rl1]);
            }

            const int r0 = base + cwid * 16 + qrow;
            const int r1 = r0 + 8;
            int cur = wcur;

            for (int l = 0; l < 7; l++) {
                // stage next weights (layer l+1, or layer 0 for next tile) into other buf
                const bool do_stage = (l < 6) || (k + 1 < nt);
                if (do_stage) {
                    const int nl = (l < 6) ? l + 1 : 0;
                    const uint32_t dst = sb + SM_W + (cur ^ 1) * 32768;
                    const size_t soff = (nl == 0) ? 0 : (size_t)4096 + (size_t)(nl - 1) * 32768;
                    const int cnt = (nl == 0) ? 256 : 2048;
                    for (int i = ctid; i < cnt; i += 256)
                        cp_async16(dst + 16 * i, d_wpack + soff + 16 * (size_t)i);
                    cp_commit();
                }

                const int K16 = (l == 0) ? 1 : 8;
                const uint4* wf = (const uint4*)(smem + SM_W + cur * 32768);
                const float* bs = (const float*)(smem + SM_BIAS + l * 512);

                float acc[16][4];
#pragma unroll
                for (int j = 0; j < 16; j++)
#pragma unroll
                    for (int q = 0; q < 4; q++) acc[j][q] = 0.0f;

#pragma unroll 1
                for (int ks = 0; ks < K16; ks++) {
#pragma unroll
                    for (int jp = 0; jp < 8; jp++) {
                        uint4 w = wf[(ks * 8 + jp) * 32 + lane];
                        mma_fp16(acc[2 * jp],     af[ks], w.x, w.y);
                        mma_fp16(acc[2 * jp + 1], af[ks], w.z, w.w);
                    }
                }

                if (l < 6) {
                    // bias + relu, repack D -> next-layer A fragments (lane-local)
#pragma unroll
                    for (int j = 0; j < 16; j++) {
                        float b0 = bs[8 * j + 2 * tc];
                        float b1 = bs[8 * j + 2 * tc + 1];
                        acc[j][0] = fmaxf(acc[j][0] + b0, 0.0f);
                        acc[j][1] = fmaxf(acc[j][1] + b1, 0.0f);
                        acc[j][2] = fmaxf(acc[j][2] + b0, 0.0f);
                        acc[j][3] = fmaxf(acc[j][3] + b1, 0.0f);
                    }
#pragma unroll
                    for (int t = 0; t < 8; t++) {
                        af[t][0] = cvt_f16x2(acc[2 * t][0],     acc[2 * t][1]);
                        af[t][1] = cvt_f16x2(acc[2 * t][2],     acc[2 * t][3]);
                        af[t][2] = cvt_f16x2(acc[2 * t + 1][0], acc[2 * t + 1][1]);
                        af[t][3] = cvt_f16x2(acc[2 * t + 1][2], acc[2 * t + 1][3]);
                    }
                } else {
                    float* o0 = out + (size_t)r0 * 128;
                    float* o1 = out + (size_t)r1 * 128;
#pragma unroll
                    for (int j = 0; j < 16; j++) {
                        const int col = 8 * j + 2 * tc;
                        float b0 = bs[col], b1 = bs[col + 1];
                        float2 v0 = make_float2(acc[j][0] + b0, acc[j][1] + b1);
                        float2 v1 = make_float2(acc[j][2] + b0, acc[j][3] + b1);
                        *(float2*)(o0 + col) = v0;
                        *(float2*)(o1 + col) = v1;
                    }
                }

                if (do_stage) cp_wait_all();
                CONS_BAR();       // all consumers done with wbuf[cur]; next buf ready
                cur ^= 1;
            }
            wcur = cur;   // 7 toggles -> flipped for next tile (layer 0 staged there)
        }
        __syncthreads();  // tile handoff: feats(k+1) ready, feats(k) consumed
    }
}

// ---------------- launch ----------------
extern "C" void kernel_launch(void* const* d_in, const int* in_sizes, int n_in,
                              void* d_out, int out_size) {
    const float* x    = (const float*)d_in[0];
    const float* g0   = (const float*)d_in[1];
    const float* g1   = (const float*)d_in[2];
    const float* g2   = (const float*)d_in[3];
    const float* g3   = (const float*)d_in[4];
    const float* coef = (const float*)d_in[5];

    MLPW p;
    for (int j = 0; j < 7; j++) {
        p.W[j] = (const float*)d_in[6 + 2 * j];
        p.B[j] = (const float*)d_in[7 + 2 * j];
    }
    float* out = (float*)d_out;

    cudaFuncSetAttribute(mlp_mma, cudaFuncAttributeMaxDynamicSharedMemorySize, SM_DYN);

    void* ptr;
    cudaGetSymbolAddress(&ptr, d_g0t);   float4* g0t = (float4*)ptr;
    cudaGetSymbolAddress(&ptr, d_g1t);   float4* g1t = (float4*)ptr;
    cudaGetSymbolAddress(&ptr, d_g2t);   float4* g2t = (float4*)ptr;
    cudaGetSymbolAddress(&ptr, d_g3t);   float4* g3t = (float4*)ptr;
    cudaGetSymbolAddress(&ptr, d_coeft); float4* ct  = (float4*)ptr;

    transpose_cl<<<(32 * 32 * 32 + 255) / 256, 256>>>(g0, g0t, 32 * 32 * 32);
    transpose_cl<<<(64 * 64 * 64 + 255) / 256, 256>>>(g1, g1t, 64 * 64 * 64);
    transpose_cl<<<(128 * 128 * 128 + 255) / 256, 256>>>(g2, g2t, 128 * 128 * 128);
    transpose_cl<<<(256 * 256 * 256 + 255) / 256, 256>>>(g3, g3t, 256 * 256 * 256);
    transpose_cl<<<(64 * 64 * 64 + 255) / 256, 256>>>(coef, ct, 64 * 64 * 64);

    pack_weights<<<(7 * 8 * 16 * 32 + 255) / 256, 256>>>(p);

    mlp_mma<<<148, 512, SM_DYN>>>(p, x, out);
}